// round 1
// baseline (speedup 1.0000x reference)
#include <cuda_runtime.h>
#include <cstdint>
#include <cstddef>

// ---------------------------------------------------------------------------
// CorrelatedCategoricalsLM: embed -> concat(z) -> GRU(T=128) -> vocab logits
// B=32, T=128, V=32000, E=512, H=512, DZ=256
// ---------------------------------------------------------------------------

namespace {
constexpr int kB  = 32;
constexpr int kT  = 128;
constexpr int kV  = 32000;
constexpr int kE  = 512;
constexpr int kH  = 512;
constexpr int kDZ = 256;
constexpr int kMBT = kB * kT;     // 4096 rows
constexpr int kG3H = 3 * kH;      // 1536 gates
constexpr int kLDW = kE + kDZ;    // 768 = W_ih row stride
}

// Scratch (device globals: no allocation allowed)
__device__ float g_hbuf[2][kB * kH];              // h ping-pong, [b][j]
__device__ float g_zpart[kB * kG3H];              // z @ W_ih[:,E:]^T + b_ih
__device__ float g_gi[(size_t)kMBT * kG3H];       // 25.2 MB
__device__ float g_hs[(size_t)kMBT * kH];         // 8.4 MB

// ---------------------------------------------------------------------------
// h0 = tanh(z @ W_init^T + b_init)   [32,512], K=256
// ---------------------------------------------------------------------------
__global__ void k_h0(const float* __restrict__ z,
                     const float* __restrict__ Wi,
                     const float* __restrict__ bi) {
    int idx = blockIdx.x * blockDim.x + threadIdx.x;   // 16384
    int b = idx >> 9;
    int j = idx & 511;
    const float* zr = z + b * kDZ;
    const float* wr = Wi + (size_t)j * kDZ;
    float acc = bi[j];
#pragma unroll 8
    for (int d = 0; d < kDZ; d += 4) {
        float4 zv = *(const float4*)(zr + d);
        float4 wv = *(const float4*)(wr + d);
        acc += zv.x * wv.x + zv.y * wv.y + zv.z * wv.z + zv.w * wv.w;
    }
    g_hbuf[0][b * kH + j] = tanhf(acc);
}

// ---------------------------------------------------------------------------
// zpart[b,g] = b_ih[g] + sum_d z[b,d] * W_ih[g, E+d]   [32,1536], K=256
// ---------------------------------------------------------------------------
__global__ void k_zpart(const float* __restrict__ z,
                        const float* __restrict__ W_ih,
                        const float* __restrict__ b_ih) {
    int g = blockIdx.x * blockDim.x + threadIdx.x;  // grid.x = 6, 256 thr
    int b = blockIdx.y;
    const float* zr = z + b * kDZ;
    const float* wr = W_ih + (size_t)g * kLDW + kE;
    float acc = b_ih[g];
#pragma unroll 8
    for (int d = 0; d < kDZ; d += 4) {
        float4 zv = *(const float4*)(zr + d);
        float4 wv = *(const float4*)(wr + d);
        acc += zv.x * wv.x + zv.y * wv.y + zv.z * wv.z + zv.w * wv.w;
    }
    g_zpart[b * kG3H + g] = acc;
}

// ---------------------------------------------------------------------------
// C[M,N] = A' @ B^T (+ rowAdd broadcast)
//   A' row m = A[gidx[m]] if GATHER else A[m]         (row-major, lda)
//   B row-major [N, K] with row stride ldb
//   HASADD: C[m,n] += rowAdd[(m>>7)*N + n]   (broadcast z-part over T)
// 128x128 tile, BK=16, 256 threads, 8x8 microtile (split 4+4 fragments).
// ---------------------------------------------------------------------------
template <bool GATHER, bool HASADD>
__global__ __launch_bounds__(256, 2)
void k_gemm(const float* __restrict__ A, const float* __restrict__ Bm,
            float* __restrict__ C, const float* __restrict__ rowAdd,
            const int* __restrict__ gidx,
            int N, int K, int lda, int ldb) {
    __shared__ float As[16][132];
    __shared__ float Bs[16][132];
    __shared__ int   xs[128];

    const int tid = threadIdx.x;
    const int m0 = blockIdx.y * 128;
    const int n0 = blockIdx.x * 128;
    const int tx = tid & 15;   // n-quad
    const int ty = tid >> 4;   // m-quad

    if (tid < 128) xs[tid] = GATHER ? gidx[m0 + tid] : (m0 + tid);
    __syncthreads();

    float acc[8][8];
#pragma unroll
    for (int i = 0; i < 8; i++)
#pragma unroll
        for (int j = 0; j < 8; j++) acc[i][j] = 0.f;

    for (int k0 = 0; k0 < K; k0 += 16) {
#pragma unroll
        for (int i = 0; i < 2; i++) {
            int f = i * 256 + tid;        // [0,512)
            int r = f >> 2;               // tile row [0,128)
            int kq = f & 3;               // 4-float chunk of the 16 k's
            const float4 av =
                *(const float4*)(A + (size_t)xs[r] * lda + k0 + kq * 4);
            As[kq * 4 + 0][r] = av.x;
            As[kq * 4 + 1][r] = av.y;
            As[kq * 4 + 2][r] = av.z;
            As[kq * 4 + 3][r] = av.w;
            const float4 bv =
                *(const float4*)(Bm + (size_t)(n0 + r) * ldb + k0 + kq * 4);
            Bs[kq * 4 + 0][r] = bv.x;
            Bs[kq * 4 + 1][r] = bv.y;
            Bs[kq * 4 + 2][r] = bv.z;
            Bs[kq * 4 + 3][r] = bv.w;
        }
        __syncthreads();
#pragma unroll
        for (int k = 0; k < 16; k++) {
            float ra[8], rb[8];
            *(float4*)(ra)     = *(const float4*)&As[k][ty * 4];
            *(float4*)(ra + 4) = *(const float4*)&As[k][64 + ty * 4];
            *(float4*)(rb)     = *(const float4*)&Bs[k][tx * 4];
            *(float4*)(rb + 4) = *(const float4*)&Bs[k][64 + tx * 4];
#pragma unroll
            for (int i = 0; i < 8; i++)
#pragma unroll
                for (int j = 0; j < 8; j++) acc[i][j] += ra[i] * rb[j];
        }
        __syncthreads();
    }

#pragma unroll
    for (int i = 0; i < 8; i++) {
        int mloc = (i < 4) ? (ty * 4 + i) : (64 + ty * 4 + (i - 4));
        int m = m0 + mloc;
        float v[8];
#pragma unroll
        for (int j = 0; j < 8; j++) v[j] = acc[i][j];
        if (HASADD) {
            const float* ar = rowAdd + (size_t)(m >> 7) * N + n0;
#pragma unroll
            for (int j = 0; j < 4; j++) {
                v[j]     += ar[tx * 4 + j];
                v[4 + j] += ar[64 + tx * 4 + j];
            }
        }
        float* crow = C + (size_t)m * N + n0;
        *(float4*)(crow + tx * 4)      = make_float4(v[0], v[1], v[2], v[3]);
        *(float4*)(crow + 64 + tx * 4) = make_float4(v[4], v[5], v[6], v[7]);
    }
}

// ---------------------------------------------------------------------------
// One GRU time step. grid = (64 j-chunks of 8, 2 b-halves of 16), block = 128.
// Thread (b, j): 3 dot products over K=512 with h rows cached in padded smem.
// ---------------------------------------------------------------------------
__global__ __launch_bounds__(128)
void k_gru_step(const float* __restrict__ hprev, float* __restrict__ hnext,
                const float* __restrict__ gi, const float* __restrict__ W_hh,
                const float* __restrict__ b_hh, float* __restrict__ hs, int t) {
    __shared__ float hsm[16][kH + 4];   // pad to 516 -> conflict-free strided reads

    const int tid = threadIdx.x;
    const int bb = blockIdx.y * 16;
    const int bl = tid & 15;
    const int jl = tid >> 4;                 // 0..7
    const int j = blockIdx.x * 8 + jl;
    const int b = bb + bl;

    // cooperative load of 16 h rows (32 KB) into smem
    for (int i = tid; i < 16 * (kH / 4); i += 128) {
        int r = i >> 7;        // 128 float4 per row
        int c = i & 127;
        *(float4*)&hsm[r][c * 4] =
            *(const float4*)&hprev[(bb + r) * kH + c * 4];
    }
    __syncthreads();

    const float* wr = W_hh + (size_t)j * kH;
    const float* wz = W_hh + (size_t)(kH + j) * kH;
    const float* wn = W_hh + (size_t)(2 * kH + j) * kH;

    float ar = 0.f, az = 0.f, an = 0.f;
#pragma unroll 8
    for (int k = 0; k < kH; k += 4) {
        float4 hv  = *(const float4*)&hsm[bl][k];
        float4 wrv = *(const float4*)(wr + k);
        float4 wzv = *(const float4*)(wz + k);
        float4 wnv = *(const float4*)(wn + k);
        ar += hv.x * wrv.x + hv.y * wrv.y + hv.z * wrv.z + hv.w * wrv.w;
        az += hv.x * wzv.x + hv.y * wzv.y + hv.z * wzv.z + hv.w * wzv.w;
        an += hv.x * wnv.x + hv.y * wnv.y + hv.z * wnv.z + hv.w * wnv.w;
    }

    const float* gib = gi + ((size_t)b * kT + t) * kG3H;
    float ir = gib[j];
    float iz = gib[kH + j];
    float in_ = gib[2 * kH + j];

    float r  = 1.f / (1.f + expf(-(ir + ar + b_hh[j])));
    float zg = 1.f / (1.f + expf(-(iz + az + b_hh[kH + j])));
    float n  = tanhf(in_ + r * (an + b_hh[2 * kH + j]));

    float hp = hsm[bl][j];
    float hn = (1.f - zg) * n + zg * hp;

    hnext[b * kH + j] = hn;
    hs[((size_t)b * kT + t) * kH + j] = hn;
}

// ---------------------------------------------------------------------------
// kernel_launch: graph-capturable, allocation-free
// ---------------------------------------------------------------------------
extern "C" void kernel_launch(void* const* d_in, const int* in_sizes, int n_in,
                              void* d_out, int out_size) {
    const int*   x      = (const int*)  d_in[0];
    const float* z      = (const float*)d_in[1];
    const float* emb    = (const float*)d_in[2];
    const float* W_init = (const float*)d_in[3];
    const float* b_init = (const float*)d_in[4];
    const float* W_ih   = (const float*)d_in[5];
    const float* W_hh   = (const float*)d_in[6];
    const float* b_ih   = (const float*)d_in[7];
    const float* b_hh   = (const float*)d_in[8];
    const float* W_out  = (const float*)d_in[9];
    float* out = (float*)d_out;

    float *p_hbuf, *p_zpart, *p_gi, *p_hs;
    cudaGetSymbolAddress((void**)&p_hbuf,  g_hbuf);
    cudaGetSymbolAddress((void**)&p_zpart, g_zpart);
    cudaGetSymbolAddress((void**)&p_gi,    g_gi);
    cudaGetSymbolAddress((void**)&p_hs,    g_hs);

    // 1. h0 and z-part (tiny)
    k_h0<<<64, 256>>>(z, W_init, b_init);
    k_zpart<<<dim3(kG3H / 256, kB), 256>>>(z, W_ih, b_ih);

    // 2. gi = emb[x] @ W_ih[:, :E]^T  (+ zpart broadcast over T, incl. b_ih)
    //    M=4096, N=1536, K=512, lda=512(emb), ldb=768(W_ih)
    k_gemm<true, true><<<dim3(kG3H / 128, kMBT / 128), 256>>>(
        emb, W_ih, p_gi, p_zpart, x, kG3H, kE, kE, kLDW);

    // 3. GRU scan: 128 sequential steps, ping-pong hidden state
    for (int t = 0; t < kT; t++) {
        const float* hp = p_hbuf + (size_t)(t & 1) * kB * kH;
        float*       hn = p_hbuf + (size_t)((t + 1) & 1) * kB * kH;
        k_gru_step<<<dim3(kH / 8, 2), 128>>>(hp, hn, p_gi, W_hh, b_hh, p_hs, t);
    }

    // 4. logits = hs @ W_out^T   M=4096, N=32000, K=512
    k_gemm<false, false><<<dim3(kV / 128, kMBT / 128), 256>>>(
        p_hs, W_out, out, nullptr, nullptr, kV, kH, kH, kH);
}

// round 2
// speedup vs baseline: 1.2823x; 1.2823x over previous
#include <cuda_runtime.h>
#include <cstdint>
#include <cstddef>

// ---------------------------------------------------------------------------
// CorrelatedCategoricalsLM: embed -> concat(z) -> GRU(T=128) -> vocab logits
// B=32, T=128, V=32000, E=512, H=512, DZ=256
// ---------------------------------------------------------------------------

namespace {
constexpr int kB  = 32;
constexpr int kT  = 128;
constexpr int kV  = 32000;
constexpr int kE  = 512;
constexpr int kH  = 512;
constexpr int kDZ = 256;
constexpr int kMBT = kB * kT;     // 4096 rows
constexpr int kG3H = 3 * kH;      // 1536 gates
constexpr int kLDW = kE + kDZ;    // 768 = W_ih row stride

constexpr int GRU_NBLK = 128;     // persistent blocks (1 per SM, <=148)
constexpr int JPB = kH / GRU_NBLK;// 4 hidden units per block
constexpr int HPAD = 514;         // h smem row stride (s%32==2 -> 2-way max)
}

using u64 = unsigned long long;

__device__ __forceinline__ u64 pack2(float x, float y) {
    u64 r; asm("mov.b64 %0, {%1, %2};" : "=l"(r) : "f"(x), "f"(y)); return r;
}
__device__ __forceinline__ u64 fma2(u64 a, u64 b, u64 c) {
    u64 d; asm("fma.rn.f32x2 %0, %1, %2, %3;" : "=l"(d) : "l"(a), "l"(b), "l"(c));
    return d;
}
__device__ __forceinline__ float2 unpack2(u64 v) {
    float2 f; asm("mov.b64 {%0, %1}, %2;" : "=f"(f.x), "=f"(f.y) : "l"(v));
    return f;
}

// Scratch (device globals: no allocation allowed)
__device__ float g_hbuf[2][kB * kH];              // h ping-pong, [b][j]
__device__ float g_zpart[kB * kG3H];              // z @ W_ih[:,E:]^T + b_ih
__device__ float g_gi[(size_t)kMBT * kG3H];       // 25.2 MB
__device__ float g_hs[(size_t)kMBT * kH];         // 8.4 MB
__device__ unsigned g_bar_count;                  // software grid barrier
__device__ unsigned g_bar_epoch;                  // monotonic, wrap-safe

// ---------------------------------------------------------------------------
// h0 = tanh(z @ W_init^T + b_init)   [32,512], K=256  -> g_hbuf[0]
// ---------------------------------------------------------------------------
__global__ void k_h0(const float* __restrict__ z,
                     const float* __restrict__ Wi,
                     const float* __restrict__ bi) {
    int idx = blockIdx.x * blockDim.x + threadIdx.x;   // 16384
    int b = idx >> 9;
    int j = idx & 511;
    const float* zr = z + b * kDZ;
    const float* wr = Wi + (size_t)j * kDZ;
    float acc = bi[j];
#pragma unroll 8
    for (int d = 0; d < kDZ; d += 4) {
        float4 zv = *(const float4*)(zr + d);
        float4 wv = *(const float4*)(wr + d);
        acc += zv.x * wv.x + zv.y * wv.y + zv.z * wv.z + zv.w * wv.w;
    }
    g_hbuf[0][b * kH + j] = tanhf(acc);
}

// ---------------------------------------------------------------------------
// zpart[b,g] = b_ih[g] + sum_d z[b,d] * W_ih[g, E+d]   [32,1536], K=256
// ---------------------------------------------------------------------------
__global__ void k_zpart(const float* __restrict__ z,
                        const float* __restrict__ W_ih,
                        const float* __restrict__ b_ih) {
    int g = blockIdx.x * blockDim.x + threadIdx.x;
    int b = blockIdx.y;
    const float* zr = z + b * kDZ;
    const float* wr = W_ih + (size_t)g * kLDW + kE;
    float acc = b_ih[g];
#pragma unroll 8
    for (int d = 0; d < kDZ; d += 4) {
        float4 zv = *(const float4*)(zr + d);
        float4 wv = *(const float4*)(wr + d);
        acc += zv.x * wv.x + zv.y * wv.y + zv.z * wv.z + zv.w * wv.w;
    }
    g_zpart[b * kG3H + g] = acc;
}

// ---------------------------------------------------------------------------
// C[M,N] = A' @ B^T (+ rowAdd broadcast), fp32 with packed f32x2 FFMA.
//   A' row m = A[gidx[m]] if GATHER else A[m]
//   HASADD: C[m,n] += rowAdd[(m>>7)*N + n]
// 128x128 tile, BK=16, 256 threads, 8x8 microtile.
// ---------------------------------------------------------------------------
template <bool GATHER, bool HASADD>
__global__ __launch_bounds__(256, 2)
void k_gemm(const float* __restrict__ A, const float* __restrict__ Bm,
            float* __restrict__ C, const float* __restrict__ rowAdd,
            const int* __restrict__ gidx,
            int N, int K, int lda, int ldb) {
    __shared__ float As[16][132];
    __shared__ float Bs[16][132];
    __shared__ int   xs[128];

    const int tid = threadIdx.x;
    const int m0 = blockIdx.y * 128;
    const int n0 = blockIdx.x * 128;
    const int tx = tid & 15;   // n-quad
    const int ty = tid >> 4;   // m-quad

    if (tid < 128) xs[tid] = GATHER ? gidx[m0 + tid] : (m0 + tid);
    __syncthreads();

    u64 acc2[8][4];
#pragma unroll
    for (int i = 0; i < 8; i++)
#pragma unroll
        for (int j = 0; j < 4; j++) acc2[i][j] = 0ull;

    for (int k0 = 0; k0 < K; k0 += 16) {
#pragma unroll
        for (int i = 0; i < 2; i++) {
            int f = i * 256 + tid;        // [0,512)
            int r = f >> 2;               // tile row [0,128)
            int kq = f & 3;               // 4-float chunk of the 16 k's
            const float4 av =
                *(const float4*)(A + (size_t)xs[r] * lda + k0 + kq * 4);
            As[kq * 4 + 0][r] = av.x;
            As[kq * 4 + 1][r] = av.y;
            As[kq * 4 + 2][r] = av.z;
            As[kq * 4 + 3][r] = av.w;
            const float4 bv =
                *(const float4*)(Bm + (size_t)(n0 + r) * ldb + k0 + kq * 4);
            Bs[kq * 4 + 0][r] = bv.x;
            Bs[kq * 4 + 1][r] = bv.y;
            Bs[kq * 4 + 2][r] = bv.z;
            Bs[kq * 4 + 3][r] = bv.w;
        }
        __syncthreads();
#pragma unroll
        for (int k = 0; k < 16; k++) {
            float ra[8];
            u64 rb2[4];
            *(float4*)(ra)     = *(const float4*)&As[k][ty * 4];
            *(float4*)(ra + 4) = *(const float4*)&As[k][64 + ty * 4];
            {   // B fragments already pair-packed in smem (16B aligned)
                ulonglong2 b0 = *(const ulonglong2*)&Bs[k][tx * 4];
                ulonglong2 b1 = *(const ulonglong2*)&Bs[k][64 + tx * 4];
                rb2[0] = b0.x; rb2[1] = b0.y; rb2[2] = b1.x; rb2[3] = b1.y;
            }
#pragma unroll
            for (int i = 0; i < 8; i++) {
                u64 ra2 = pack2(ra[i], ra[i]);
#pragma unroll
                for (int j = 0; j < 4; j++)
                    acc2[i][j] = fma2(ra2, rb2[j], acc2[i][j]);
            }
        }
        __syncthreads();
    }

#pragma unroll
    for (int i = 0; i < 8; i++) {
        int mloc = (i < 4) ? (ty * 4 + i) : (64 + ty * 4 + (i - 4));
        int m = m0 + mloc;
        float v[8];
#pragma unroll
        for (int j = 0; j < 4; j++) {
            float2 f = unpack2(acc2[i][j]);
            v[2 * j] = f.x; v[2 * j + 1] = f.y;
        }
        if (HASADD) {
            const float* ar = rowAdd + (size_t)(m >> 7) * N + n0;
#pragma unroll
            for (int j = 0; j < 4; j++) {
                v[j]     += ar[tx * 4 + j];
                v[4 + j] += ar[64 + tx * 4 + j];
            }
        }
        float* crow = C + (size_t)m * N + n0;
        *(float4*)(crow + tx * 4)      = make_float4(v[0], v[1], v[2], v[3]);
        *(float4*)(crow + 64 + tx * 4) = make_float4(v[4], v[5], v[6], v[7]);
    }
}

// ---------------------------------------------------------------------------
// Persistent GRU scan: 128 blocks x 256 threads, all timesteps in one launch.
// Block owns JPB=4 hidden units; W_hh slice lives in smem for all 128 steps.
// Thread (b, jj, khalf) computes half-K partials of the 3 gate dots (f32x2).
// Software grid barrier (count+epoch) between steps; h via L2 (ldcg/stcg).
// ---------------------------------------------------------------------------
__global__ __launch_bounds__(256, 1)
void k_gru_persistent(const float* __restrict__ gi,
                      const float* __restrict__ W_hh,
                      const float* __restrict__ b_hh,
                      float* __restrict__ hbuf,   // [2][B*H]
                      float* __restrict__ hs) {   // [B*T*H]
    extern __shared__ float sm[];
    float* wsm = sm;                          // [3][JPB][512]
    float* hsm = sm + 3 * JPB * kH;           // [32][HPAD]
    float* psm = hsm + kB * HPAD;             // [32][JPB][3]

    const int tid = threadIdx.x;
    const int j0 = blockIdx.x * JPB;
    const int b  = tid & 31;
    const int jj = (tid >> 5) & (JPB - 1);
    const int kh = tid >> 7;                  // 0 or 1

    // Load this block's W_hh slice once (reused for all 128 steps).
    for (int i = tid; i < 3 * JPB * (kH / 4); i += 256) {
        int g   = i / (JPB * (kH / 4));
        int rem = i - g * JPB * (kH / 4);
        int jw  = rem >> 7;                   // kH/4 = 128
        int c   = (rem & 127) << 2;
        float4 v = *(const float4*)(W_hh + (size_t)(g * kH + j0 + jw) * kH + c);
        float* d = wsm + (g * JPB + jw) * kH + c;
        d[0] = v.x; d[1] = v.y; d[2] = v.z; d[3] = v.w;
    }

    const float* wr = wsm + (0 * JPB + jj) * kH + kh * 256;
    const float* wz = wsm + (1 * JPB + jj) * kH + kh * 256;
    const float* wn = wsm + (2 * JPB + jj) * kH + kh * 256;
    const int j = j0 + jj;
    const float bhr = b_hh[j];
    const float bhz = b_hh[kH + j];
    const float bhn = b_hh[2 * kH + j];
    __syncthreads();

    for (int t = 0; t < kT; t++) {
        const float* hp = hbuf + (size_t)(t & 1) * (kB * kH);
        // stage h[32][512] into padded smem (L2-coherent loads)
        for (int i = tid; i < kB * (kH / 4); i += 256) {
            int r = i >> 7;
            int c = (i & 127) << 2;
            float4 v = __ldcg((const float4*)(hp + r * kH + c));
            float* d = hsm + r * HPAD + c;
            d[0] = v.x; d[1] = v.y; d[2] = v.z; d[3] = v.w;
        }
        __syncthreads();

        const float* hrow = hsm + b * HPAD + kh * 256;
        u64 ar = 0ull, az = 0ull, an = 0ull;
#pragma unroll 8
        for (int k = 0; k < 256; k += 2) {
            u64 h2 = *(const u64*)(hrow + k);
            ar = fma2(h2, *(const u64*)(wr + k), ar);
            az = fma2(h2, *(const u64*)(wz + k), az);
            an = fma2(h2, *(const u64*)(wn + k), an);
        }
        float2 f;
        f = unpack2(ar); float pr = f.x + f.y;
        f = unpack2(az); float pz = f.x + f.y;
        f = unpack2(an); float pn = f.x + f.y;

        if (kh == 1) {
            float* p = psm + (b * JPB + jj) * 3;
            p[0] = pr; p[1] = pz; p[2] = pn;
        }
        __syncthreads();
        if (kh == 0) {
            const float* p = psm + (b * JPB + jj) * 3;
            pr += p[0]; pz += p[1]; pn += p[2];
            const float* gib = gi + ((size_t)b * kT + t) * kG3H;
            float rg = 1.f / (1.f + expf(-(gib[j] + pr + bhr)));
            float zg = 1.f / (1.f + expf(-(gib[kH + j] + pz + bhz)));
            float n  = tanhf(gib[2 * kH + j] + rg * (pn + bhn));
            float hprev = hsm[b * HPAD + j];
            float hn = (1.f - zg) * n + zg * hprev;
            float* hnx = hbuf + (size_t)((t + 1) & 1) * (kB * kH);
            __stcg(hnx + b * kH + j, hn);
            __stcg(hs + ((size_t)b * kT + t) * kH + j, hn);
        }
        // ---- grid barrier ----
        __syncthreads();
        __threadfence();
        if (tid == 0) {
            unsigned e0 = *((volatile unsigned*)&g_bar_epoch);
            unsigned a = atomicAdd(&g_bar_count, 1u);
            if (a == GRU_NBLK - 1) {
                g_bar_count = 0;
                __threadfence();
                atomicAdd(&g_bar_epoch, 1u);
            } else {
                while (*((volatile unsigned*)&g_bar_epoch) == e0)
                    __nanosleep(32);
                __threadfence();
            }
        }
        __syncthreads();
    }
}

// ---------------------------------------------------------------------------
// kernel_launch: graph-capturable, allocation-free
// ---------------------------------------------------------------------------
extern "C" void kernel_launch(void* const* d_in, const int* in_sizes, int n_in,
                              void* d_out, int out_size) {
    const int*   x      = (const int*)  d_in[0];
    const float* z      = (const float*)d_in[1];
    const float* emb    = (const float*)d_in[2];
    const float* W_init = (const float*)d_in[3];
    const float* b_init = (const float*)d_in[4];
    const float* W_ih   = (const float*)d_in[5];
    const float* W_hh   = (const float*)d_in[6];
    const float* b_ih   = (const float*)d_in[7];
    const float* b_hh   = (const float*)d_in[8];
    const float* W_out  = (const float*)d_in[9];
    float* out = (float*)d_out;

    float *p_hbuf, *p_zpart, *p_gi, *p_hs;
    cudaGetSymbolAddress((void**)&p_hbuf,  g_hbuf);
    cudaGetSymbolAddress((void**)&p_zpart, g_zpart);
    cudaGetSymbolAddress((void**)&p_gi,    g_gi);
    cudaGetSymbolAddress((void**)&p_hs,    g_hs);

    const int gru_smem = (3 * JPB * kH + kB * HPAD + kB * JPB * 3) * 4;
    cudaFuncSetAttribute(k_gru_persistent,
                         cudaFuncAttributeMaxDynamicSharedMemorySize, gru_smem);

    // 1. h0 and z-part (tiny)
    k_h0<<<64, 256>>>(z, W_init, b_init);
    k_zpart<<<dim3(kG3H / 256, kB), 256>>>(z, W_ih, b_ih);

    // 2. gi = emb[x] @ W_ih[:, :E]^T  (+ zpart broadcast over T, incl. b_ih)
    k_gemm<true, true><<<dim3(kG3H / 128, kMBT / 128), 256>>>(
        emb, W_ih, p_gi, p_zpart, x, kG3H, kE, kE, kLDW);

    // 3. GRU scan: single persistent kernel, 128 steps internal
    k_gru_persistent<<<GRU_NBLK, 256, gru_smem>>>(
        p_gi, W_hh, b_hh, p_hbuf, p_hs);

    // 4. logits = hs @ W_out^T   M=4096, N=32000, K=512
    k_gemm<false, false><<<dim3(kV / 128, kMBT / 128), 256>>>(
        p_hs, W_out, out, nullptr, nullptr, kV, kH, kH, kH);
}

// round 6
// speedup vs baseline: 2.0442x; 1.5942x over previous
#include <cuda_runtime.h>
#include <cuda_bf16.h>
#include <cstdint>
#include <cstddef>

// ---------------------------------------------------------------------------
// CorrelatedCategoricalsLM: embed -> concat(z) -> GRU(T=128) -> vocab logits
// B=32, T=128, V=32000, E=512, H=512, DZ=256
// Logits GEMM: bf16 hi/lo split (3 cross terms folded into one K=1536 GEMM)
// on mma.sync m16n8k16 (arch-neutral; tcgen05 unavailable at sm_100 target).
// ---------------------------------------------------------------------------

namespace {
constexpr int kB  = 32;
constexpr int kT  = 128;
constexpr int kV  = 32000;
constexpr int kE  = 512;
constexpr int kH  = 512;
constexpr int kDZ = 256;
constexpr int kMBT = kB * kT;     // 4096 rows
constexpr int kG3H = 3 * kH;      // 1536 gates
constexpr int kLDW = kE + kDZ;    // 768 = W_ih row stride
constexpr int kKV = 1536;         // virtual K (3 x 512)

constexpr int GRU_NBLK = 128;     // persistent blocks
constexpr int HPAD = 514;         // h smem row stride

// logits GEMM tiling
constexpr int BM = 128, BN = 256, BK = 64;
constexpr int NSTAGES = kKV / BK;             // 24
constexpr int SMEM_A_ST = BM * 128;           // 16 KB (BK*2B = 128B rows)
constexpr int SMEM_B_ST = BN * 128;           // 32 KB
constexpr int SMEM_ST   = SMEM_A_ST + SMEM_B_ST;   // 48 KB
constexpr int SMEM_LOGITS = 2 * SMEM_ST;      // 96 KB
}

using u64 = unsigned long long;

__device__ __forceinline__ u64 fma2(u64 a, u64 b, u64 c) {
    u64 d; asm("fma.rn.f32x2 %0, %1, %2, %3;" : "=l"(d) : "l"(a), "l"(b), "l"(c));
    return d;
}
__device__ __forceinline__ float2 unpack2(u64 v) {
    float2 f; asm("mov.b64 {%0, %1}, %2;" : "=f"(f.x), "=f"(f.y) : "l"(v));
    return f;
}
__device__ __forceinline__ uint32_t smem_u32(const void* p) {
    uint32_t a;
    asm("{ .reg .u64 t; cvta.to.shared.u64 t, %1; cvt.u32.u64 %0, t; }"
        : "=r"(a) : "l"(p));
    return a;
}
__device__ __forceinline__ void ldsm4(uint32_t& r0, uint32_t& r1,
                                      uint32_t& r2, uint32_t& r3, uint32_t a) {
    asm volatile("ldmatrix.sync.aligned.m8n8.x4.shared.b16 {%0,%1,%2,%3}, [%4];"
        : "=r"(r0), "=r"(r1), "=r"(r2), "=r"(r3) : "r"(a));
}
__device__ __forceinline__ void mma16816(float* c, const uint32_t* a,
                                         const uint32_t* b) {
    asm volatile("mma.sync.aligned.m16n8k16.row.col.f32.bf16.bf16.f32 "
        "{%0,%1,%2,%3}, {%4,%5,%6,%7}, {%8,%9}, {%0,%1,%2,%3};"
        : "+f"(c[0]), "+f"(c[1]), "+f"(c[2]), "+f"(c[3])
        : "r"(a[0]), "r"(a[1]), "r"(a[2]), "r"(a[3]), "r"(b[0]), "r"(b[1]));
}
__device__ __forceinline__ void cp_async16(uint32_t dst, const void* src) {
    asm volatile("cp.async.cg.shared.global [%0], [%1], 16;"
                 :: "r"(dst), "l"(src) : "memory");
}

// ---------------------------------------------------------------------------
// Scratch (device globals)
// ---------------------------------------------------------------------------
__device__ __align__(256) float g_hbuf[2][kB * kH];
__device__ __align__(256) float g_zpart[kB * kG3H];
__device__ __align__(256) float g_gi[(size_t)kMBT * kG3H];        // 25.2 MB
__device__ __align__(256) float g_hs[(size_t)kMBT * kH];          // 8.4 MB
__device__ __align__(256) __nv_bfloat16 g_a2[(size_t)kMBT * kKV]; // 12.6 MB
__device__ __align__(256) __nv_bfloat16 g_b2[(size_t)kV * kKV];   // 98.3 MB
__device__ unsigned g_bar_count;
__device__ unsigned g_bar_epoch;

// ---------------------------------------------------------------------------
// h0 = tanh(z @ W_init^T + b_init)
// ---------------------------------------------------------------------------
__global__ void k_h0(const float* __restrict__ z,
                     const float* __restrict__ Wi,
                     const float* __restrict__ bi) {
    int idx = blockIdx.x * blockDim.x + threadIdx.x;
    int b = idx >> 9;
    int j = idx & 511;
    const float* zr = z + b * kDZ;
    const float* wr = Wi + (size_t)j * kDZ;
    float acc = bi[j];
#pragma unroll 8
    for (int d = 0; d < kDZ; d += 4) {
        float4 zv = *(const float4*)(zr + d);
        float4 wv = *(const float4*)(wr + d);
        acc += zv.x * wv.x + zv.y * wv.y + zv.z * wv.z + zv.w * wv.w;
    }
    g_hbuf[0][b * kH + j] = tanhf(acc);
}

// ---------------------------------------------------------------------------
// zpart[b,g] = b_ih[g] + z[b,:] . W_ih[g, E:]
// ---------------------------------------------------------------------------
__global__ void k_zpart(const float* __restrict__ z,
                        const float* __restrict__ W_ih,
                        const float* __restrict__ b_ih) {
    int g = blockIdx.x * blockDim.x + threadIdx.x;
    int b = blockIdx.y;
    const float* zr = z + b * kDZ;
    const float* wr = W_ih + (size_t)g * kLDW + kE;
    float acc = b_ih[g];
#pragma unroll 8
    for (int d = 0; d < kDZ; d += 4) {
        float4 zv = *(const float4*)(zr + d);
        float4 wv = *(const float4*)(wr + d);
        acc += zv.x * wv.x + zv.y * wv.y + zv.z * wv.z + zv.w * wv.w;
    }
    g_zpart[b * kG3H + g] = acc;
}

// ---------------------------------------------------------------------------
// Scalar fp32 SIMT GEMM — used only for gi (6.4 GF).
// ---------------------------------------------------------------------------
__global__ __launch_bounds__(256, 2)
void k_gemm_gi(const float* __restrict__ A, const float* __restrict__ Bm,
               float* __restrict__ C, const float* __restrict__ rowAdd,
               const int* __restrict__ gidx,
               int N, int K, int lda, int ldb) {
    __shared__ float As[16][132];
    __shared__ float Bs[16][132];
    __shared__ int   xs[128];

    const int tid = threadIdx.x;
    const int m0 = blockIdx.y * 128;
    const int n0 = blockIdx.x * 128;
    const int tx = tid & 15;
    const int ty = tid >> 4;

    if (tid < 128) xs[tid] = gidx[m0 + tid];
    __syncthreads();

    float acc[8][8];
#pragma unroll
    for (int i = 0; i < 8; i++)
#pragma unroll
        for (int j = 0; j < 8; j++) acc[i][j] = 0.f;

    for (int k0 = 0; k0 < K; k0 += 16) {
#pragma unroll
        for (int i = 0; i < 2; i++) {
            int f = i * 256 + tid;
            int r = f >> 2;
            int kq = f & 3;
            const float4 av = *(const float4*)(A + (size_t)xs[r] * lda + k0 + kq * 4);
            As[kq * 4 + 0][r] = av.x; As[kq * 4 + 1][r] = av.y;
            As[kq * 4 + 2][r] = av.z; As[kq * 4 + 3][r] = av.w;
            const float4 bv = *(const float4*)(Bm + (size_t)(n0 + r) * ldb + k0 + kq * 4);
            Bs[kq * 4 + 0][r] = bv.x; Bs[kq * 4 + 1][r] = bv.y;
            Bs[kq * 4 + 2][r] = bv.z; Bs[kq * 4 + 3][r] = bv.w;
        }
        __syncthreads();
#pragma unroll
        for (int k = 0; k < 16; k++) {
            float ra[8], rb[8];
            *(float4*)(ra)     = *(const float4*)&As[k][ty * 4];
            *(float4*)(ra + 4) = *(const float4*)&As[k][64 + ty * 4];
            *(float4*)(rb)     = *(const float4*)&Bs[k][tx * 4];
            *(float4*)(rb + 4) = *(const float4*)&Bs[k][64 + tx * 4];
#pragma unroll
            for (int i = 0; i < 8; i++)
#pragma unroll
                for (int j = 0; j < 8; j++) acc[i][j] += ra[i] * rb[j];
        }
        __syncthreads();
    }

#pragma unroll
    for (int i = 0; i < 8; i++) {
        int mloc = (i < 4) ? (ty * 4 + i) : (64 + ty * 4 + (i - 4));
        int m = m0 + mloc;
        float v[8];
#pragma unroll
        for (int j = 0; j < 8; j++) v[j] = acc[i][j];
        const float* ar = rowAdd + (size_t)(m >> 7) * N + n0;
#pragma unroll
        for (int j = 0; j < 4; j++) {
            v[j]     += ar[tx * 4 + j];
            v[4 + j] += ar[64 + tx * 4 + j];
        }
        float* crow = C + (size_t)m * N + n0;
        *(float4*)(crow + tx * 4)      = make_float4(v[0], v[1], v[2], v[3]);
        *(float4*)(crow + 64 + tx * 4) = make_float4(v[4], v[5], v[6], v[7]);
    }
}

// ---------------------------------------------------------------------------
// hi/lo split into the 3-segment layout.
// mode A (0): dst row = [hi | hi | lo];  mode B (1): dst row = [hi | lo | hi]
// One block per row, 256 threads, thread handles 2 source elems.
// ---------------------------------------------------------------------------
template <int MODE>
__global__ void k_cvt3(const float* __restrict__ src, __nv_bfloat16* __restrict__ dst) {
    int n = blockIdx.x;
    int k2 = threadIdx.x;            // 0..255
    float2 v = *(const float2*)(src + (size_t)n * 512 + k2 * 2);
    __nv_bfloat16 hx = __float2bfloat16(v.x);
    __nv_bfloat16 hy = __float2bfloat16(v.y);
    __nv_bfloat16 lx = __float2bfloat16(v.x - __bfloat162float(hx));
    __nv_bfloat16 ly = __float2bfloat16(v.y - __bfloat162float(hy));
    __nv_bfloat162 hi2(hx, hy), lo2(lx, ly);
    __nv_bfloat162* o = (__nv_bfloat162*)(dst + (size_t)n * kKV);
    o[k2] = hi2;
    if (MODE == 0) { o[256 + k2] = hi2; o[512 + k2] = lo2; }
    else           { o[256 + k2] = lo2; o[512 + k2] = hi2; }
}

// ---------------------------------------------------------------------------
// Persistent GRU: 128 blocks x 512 threads. Block owns 4 hidden units.
// Thread = (b, jj, kq): K-quarter partials of 3 gate dots via f32x2.
// Bounded grid barrier (no-hang).
// ---------------------------------------------------------------------------
__global__ __launch_bounds__(512, 1)
void k_gru_persistent(const float* __restrict__ gi,
                      const float* __restrict__ W_hh,
                      const float* __restrict__ b_hh,
                      float* __restrict__ hbuf,
                      float* __restrict__ hs) {
    extern __shared__ float sm[];
    float* wsm = sm;                          // [12][512]
    float* hsm = sm + 12 * kH;                // [32][HPAD]
    float* psm = hsm + kB * HPAD;             // [3][32][4][3]

    const int tid = threadIdx.x;
    const int b  = tid & 31;
    const int jj = (tid >> 5) & 3;
    const int kq = tid >> 7;                  // 0..3
    const int j0 = blockIdx.x * 4;
    const int j  = j0 + jj;

    for (int i = tid; i < 12 * (kH / 4); i += 512) {
        int row = i >> 7;
        int c   = (i & 127) << 2;
        int g = row >> 2, jw = row & 3;
        float4 v = *(const float4*)(W_hh + (size_t)(g * kH + j0 + jw) * kH + c);
        float* d = wsm + row * kH + c;
        d[0] = v.x; d[1] = v.y; d[2] = v.z; d[3] = v.w;
    }

    const float* wr = wsm + (0 + jj) * kH + kq * 128;
    const float* wz = wsm + (4 + jj) * kH + kq * 128;
    const float* wn = wsm + (8 + jj) * kH + kq * 128;
    const float bhr = b_hh[j];
    const float bhz = b_hh[kH + j];
    const float bhn = b_hh[2 * kH + j];
    __syncthreads();

    for (int t = 0; t < kT; t++) {
        const float* hp = hbuf + (size_t)(t & 1) * (kB * kH);
        for (int i = tid; i < kB * (kH / 4); i += 512) {
            int r = i >> 7;
            int c = (i & 127) << 2;
            float4 v = __ldcg((const float4*)(hp + r * kH + c));
            float* d = hsm + r * HPAD + c;
            d[0] = v.x; d[1] = v.y; d[2] = v.z; d[3] = v.w;
        }
        __syncthreads();

        const float* hrow = hsm + b * HPAD + kq * 128;
        u64 ar = 0ull, az = 0ull, an = 0ull;
#pragma unroll 8
        for (int k = 0; k < 128; k += 2) {
            u64 h2 = *(const u64*)(hrow + k);
            ar = fma2(h2, *(const u64*)(wr + k), ar);
            az = fma2(h2, *(const u64*)(wz + k), az);
            an = fma2(h2, *(const u64*)(wn + k), an);
        }
        float2 f;
        f = unpack2(ar); float pr = f.x + f.y;
        f = unpack2(az); float pz = f.x + f.y;
        f = unpack2(an); float pn = f.x + f.y;

        if (kq) {
            float* p = psm + (((kq - 1) * kB + b) * 4 + jj) * 3;
            p[0] = pr; p[1] = pz; p[2] = pn;
        }
        __syncthreads();
        if (kq == 0) {
#pragma unroll
            for (int q = 0; q < 3; q++) {
                const float* p = psm + ((q * kB + b) * 4 + jj) * 3;
                pr += p[0]; pz += p[1]; pn += p[2];
            }
            const float* gib = gi + ((size_t)b * kT + t) * kG3H;
            float rg = 1.f / (1.f + expf(-(gib[j] + pr + bhr)));
            float zg = 1.f / (1.f + expf(-(gib[kH + j] + pz + bhz)));
            float n  = tanhf(gib[2 * kH + j] + rg * (pn + bhn));
            float hprev = hsm[b * HPAD + j];
            float hn = (1.f - zg) * n + zg * hprev;
            float* hnx = hbuf + (size_t)((t + 1) & 1) * (kB * kH);
            __stcg(hnx + b * kH + j, hn);
            __stcg(hs + ((size_t)b * kT + t) * kH + j, hn);
        }
        __syncthreads();
        __threadfence();
        if (tid == 0) {
            unsigned e0 = *((volatile unsigned*)&g_bar_epoch);
            unsigned a = atomicAdd(&g_bar_count, 1u);
            if (a == GRU_NBLK - 1) {
                g_bar_count = 0;
                __threadfence();
                atomicAdd(&g_bar_epoch, 1u);
            } else {
                for (int it = 0; it < (1 << 16); it++) {
                    if (*((volatile unsigned*)&g_bar_epoch) != e0) break;
                    __nanosleep(64);
                }
                __threadfence();
            }
        }
        __syncthreads();
    }
}

// ---------------------------------------------------------------------------
// Logits GEMM: C[4096,32000] = A2[4096,1536] . B2[32000,1536]^T, bf16 mma.sync
// BM=128, BN=256, BK=64; 512 threads = 16 warps (4 m x 4 n), warp tile 32x64.
// 2-stage cp.async pipeline; SW128-style xor swizzle -> conflict-free ldmatrix.
// ---------------------------------------------------------------------------
__global__ __launch_bounds__(512, 1)
void k_logits_hmma(const __nv_bfloat16* __restrict__ A2,
                   const __nv_bfloat16* __restrict__ B2,
                   float* __restrict__ C) {
    extern __shared__ char smem[];
    const uint32_t sbase = smem_u32(smem);
    const int tid = threadIdx.x;
    const int l = tid & 31;
    const int wid = tid >> 5;
    const int wr = wid & 3;          // m warp (32 rows)
    const int wc = wid >> 2;         // n warp (64 cols)
    const int m0 = blockIdx.x * BM;
    const int n0 = blockIdx.y * BN;

    const char* Ag = (const char*)A2 + (size_t)m0 * (kKV * 2);
    const char* Bg = (const char*)B2 + (size_t)n0 * (kKV * 2);

    float acc[2][8][4];
#pragma unroll
    for (int i = 0; i < 2; i++)
#pragma unroll
        for (int j = 0; j < 8; j++)
#pragma unroll
            for (int q = 0; q < 4; q++) acc[i][j][q] = 0.f;

    // stage loader: rows of 128B (BK=64 bf16), chunks swizzled q^(r&7)
    auto load_stage = [&](int s, int buf) {
        const uint32_t sA = sbase + buf * SMEM_ST;
        const uint32_t sB = sA + SMEM_A_ST;
#pragma unroll
        for (int i = 0; i < 2; i++) {            // A: 1024 chunks / 512 thr
            int c = i * 512 + tid;
            int r = c >> 3, q = c & 7;
            const char* src = Ag + (size_t)r * (kKV * 2) + s * 128 + q * 16;
            cp_async16(sA + r * 128 + ((q ^ (r & 7)) << 4), src);
        }
#pragma unroll
        for (int i = 0; i < 4; i++) {            // B: 2048 chunks / 512 thr
            int c = i * 512 + tid;
            int r = c >> 3, q = c & 7;
            const char* src = Bg + (size_t)r * (kKV * 2) + s * 128 + q * 16;
            cp_async16(sB + r * 128 + ((q ^ (r & 7)) << 4), src);
        }
        asm volatile("cp.async.commit_group;" ::: "memory");
    };

    load_stage(0, 0);

    for (int s = 0; s < NSTAGES; s++) {
        if (s + 1 < NSTAGES) {
            load_stage(s + 1, (s + 1) & 1);
            asm volatile("cp.async.wait_group 1;" ::: "memory");
        } else {
            asm volatile("cp.async.wait_group 0;" ::: "memory");
        }
        __syncthreads();

        const uint32_t sA = sbase + (s & 1) * SMEM_ST;
        const uint32_t sB = sA + SMEM_A_ST;
        // per-lane base addrs (row&7 == l&7 for every fragment row)
        const uint32_t aRow = sA + (wr * 32 + (l & 15)) * 128;
        const uint32_t bRow = sB + (wc * 64 + (l & 7) + ((l >> 4) << 3)) * 128;

#pragma unroll
        for (int k = 0; k < 4; k++) {            // 4 k16-steps in BK=64
            const uint32_t achunk = (uint32_t)(((2 * k + (l >> 4)) ^ (l & 7)) << 4);
            const uint32_t bchunk = (uint32_t)(((2 * k + ((l >> 3) & 1)) ^ (l & 7)) << 4);
            uint32_t a[2][4];
            ldsm4(a[0][0], a[0][1], a[0][2], a[0][3], aRow + achunk);
            ldsm4(a[1][0], a[1][1], a[1][2], a[1][3], aRow + 16 * 128 + achunk);
            uint32_t b[8][2];
#pragma unroll
            for (int p = 0; p < 4; p++) {
                uint32_t r0, r1, r2, r3;
                ldsm4(r0, r1, r2, r3, bRow + p * (16 * 128) + bchunk);
                b[2 * p][0] = r0;     b[2 * p][1] = r1;
                b[2 * p + 1][0] = r2; b[2 * p + 1][1] = r3;
            }
#pragma unroll
            for (int mf = 0; mf < 2; mf++)
#pragma unroll
                for (int nf = 0; nf < 8; nf++)
                    mma16816(acc[mf][nf], a[mf], b[nf]);
        }
        __syncthreads();
    }

    // epilogue: lane layout of m16n8 accum: row = l>>2 (+8), col = 2*(l&3)
#pragma unroll
    for (int mf = 0; mf < 2; mf++) {
        const int row = m0 + wr * 32 + mf * 16 + (l >> 2);
        float* c0 = C + (size_t)row * kV + n0 + wc * 64 + 2 * (l & 3);
        float* c1 = c0 + (size_t)8 * kV;
#pragma unroll
        for (int nf = 0; nf < 8; nf++) {
            __stcs((float2*)(c0 + nf * 8), make_float2(acc[mf][nf][0], acc[mf][nf][1]));
            __stcs((float2*)(c1 + nf * 8), make_float2(acc[mf][nf][2], acc[mf][nf][3]));
        }
    }
}

// ---------------------------------------------------------------------------
// kernel_launch
// ---------------------------------------------------------------------------
extern "C" void kernel_launch(void* const* d_in, const int* in_sizes, int n_in,
                              void* d_out, int out_size) {
    const int*   x      = (const int*)  d_in[0];
    const float* z      = (const float*)d_in[1];
    const float* emb    = (const float*)d_in[2];
    const float* W_init = (const float*)d_in[3];
    const float* b_init = (const float*)d_in[4];
    const float* W_ih   = (const float*)d_in[5];
    const float* W_hh   = (const float*)d_in[6];
    const float* b_ih   = (const float*)d_in[7];
    const float* b_hh   = (const float*)d_in[8];
    const float* W_out  = (const float*)d_in[9];
    float* out = (float*)d_out;

    float *p_hbuf, *p_zpart, *p_gi, *p_hs;
    __nv_bfloat16 *p_a2, *p_b2;
    cudaGetSymbolAddress((void**)&p_hbuf,  g_hbuf);
    cudaGetSymbolAddress((void**)&p_zpart, g_zpart);
    cudaGetSymbolAddress((void**)&p_gi,    g_gi);
    cudaGetSymbolAddress((void**)&p_hs,    g_hs);
    cudaGetSymbolAddress((void**)&p_a2,    g_a2);
    cudaGetSymbolAddress((void**)&p_b2,    g_b2);

    const int gru_smem = (12 * kH + kB * HPAD + 3 * kB * 4 * 3) * 4;
    cudaFuncSetAttribute(k_gru_persistent,
                         cudaFuncAttributeMaxDynamicSharedMemorySize, gru_smem);
    cudaFuncSetAttribute(k_logits_hmma,
                         cudaFuncAttributeMaxDynamicSharedMemorySize, SMEM_LOGITS);

    // 1. tiny prologue
    k_h0<<<64, 256>>>(z, W_init, b_init);
    k_zpart<<<dim3(kG3H / 256, kB), 256>>>(z, W_ih, b_ih);

    // 2. gi = emb[x] @ W_ih[:, :E]^T + zpart
    k_gemm_gi<<<dim3(kG3H / 128, kMBT / 128), 256>>>(
        emb, W_ih, p_gi, p_zpart, x, kG3H, kE, kE, kLDW);

    // 3. W_out -> B2 = [hi | lo | hi]  (independent of GRU)
    k_cvt3<1><<<kV, 256>>>(W_out, p_b2);

    // 4. GRU scan (persistent)
    k_gru_persistent<<<GRU_NBLK, 512, gru_smem>>>(
        p_gi, W_hh, b_hh, p_hbuf, p_hs);

    // 5. hs -> A2 = [hi | hi | lo]
    k_cvt3<0><<<kMBT, 256>>>(p_hs, p_a2);

    // 6. logits: M=4096, N=32000, K=1536 bf16 HMMA
    k_logits_hmma<<<dim3(kMBT / BM, kV / BN), 512, SMEM_LOGITS>>>(
        p_a2, p_b2, out);
}

// round 7
// speedup vs baseline: 2.1291x; 1.0415x over previous
#include <cuda_runtime.h>
#include <cuda_bf16.h>
#include <cstdint>
#include <cstddef>

// ---------------------------------------------------------------------------
// CorrelatedCategoricalsLM: embed -> concat(z) -> GRU(T=128) -> vocab logits
// B=32, T=128, V=32000, E=512, H=512, DZ=256
// Logits: bf16 hi/lo split (3 cross terms in one K=1536 GEMM) on mma.sync.
// GRU: persistent 128-block kernel, spin grid barrier (no nanosleep),
//      LDS.128 inner loop, writes bf16 hi/hi/lo A2 rows directly.
// ---------------------------------------------------------------------------

namespace {
constexpr int kB  = 32;
constexpr int kT  = 128;
constexpr int kV  = 32000;
constexpr int kE  = 512;
constexpr int kH  = 512;
constexpr int kDZ = 256;
constexpr int kMBT = kB * kT;     // 4096 rows
constexpr int kG3H = 3 * kH;      // 1536 gates
constexpr int kLDW = kE + kDZ;    // 768 = W_ih row stride
constexpr int kKV = 1536;         // virtual K (3 x 512)

constexpr int GRU_NBLK = 128;     // persistent blocks
constexpr int HPAD = 516;         // h smem row stride (16B-aligned rows)

// logits GEMM tiling
constexpr int BM = 128, BN = 256, BK = 64;
constexpr int NSTAGES = kKV / BK;             // 24
constexpr int SMEM_A_ST = BM * 128;           // 16 KB
constexpr int SMEM_B_ST = BN * 128;           // 32 KB
constexpr int SMEM_ST   = SMEM_A_ST + SMEM_B_ST;
constexpr int SMEM_LOGITS = 2 * SMEM_ST;      // 96 KB
}

using u64 = unsigned long long;

__device__ __forceinline__ u64 fma2(u64 a, u64 b, u64 c) {
    u64 d; asm("fma.rn.f32x2 %0, %1, %2, %3;" : "=l"(d) : "l"(a), "l"(b), "l"(c));
    return d;
}
__device__ __forceinline__ float2 unpack2(u64 v) {
    float2 f; asm("mov.b64 {%0, %1}, %2;" : "=f"(f.x), "=f"(f.y) : "l"(v));
    return f;
}
__device__ __forceinline__ uint32_t smem_u32(const void* p) {
    uint32_t a;
    asm("{ .reg .u64 t; cvta.to.shared.u64 t, %1; cvt.u32.u64 %0, t; }"
        : "=r"(a) : "l"(p));
    return a;
}
__device__ __forceinline__ void ldsm4(uint32_t& r0, uint32_t& r1,
                                      uint32_t& r2, uint32_t& r3, uint32_t a) {
    asm volatile("ldmatrix.sync.aligned.m8n8.x4.shared.b16 {%0,%1,%2,%3}, [%4];"
        : "=r"(r0), "=r"(r1), "=r"(r2), "=r"(r3) : "r"(a));
}
__device__ __forceinline__ void mma16816(float* c, const uint32_t* a,
                                         const uint32_t* b) {
    asm volatile("mma.sync.aligned.m16n8k16.row.col.f32.bf16.bf16.f32 "
        "{%0,%1,%2,%3}, {%4,%5,%6,%7}, {%8,%9}, {%0,%1,%2,%3};"
        : "+f"(c[0]), "+f"(c[1]), "+f"(c[2]), "+f"(c[3])
        : "r"(a[0]), "r"(a[1]), "r"(a[2]), "r"(a[3]), "r"(b[0]), "r"(b[1]));
}
__device__ __forceinline__ void cp_async16(uint32_t dst, const void* src) {
    asm volatile("cp.async.cg.shared.global [%0], [%1], 16;"
                 :: "r"(dst), "l"(src) : "memory");
}

// ---------------------------------------------------------------------------
// Scratch (device globals)
// ---------------------------------------------------------------------------
__device__ __align__(256) float g_hbuf[2][kB * kH];
__device__ __align__(256) float g_zpart[kB * kG3H];
__device__ __align__(256) float g_gi[(size_t)kMBT * kG3H];        // 25.2 MB
__device__ __align__(256) __nv_bfloat16 g_a2[(size_t)kMBT * kKV]; // 12.6 MB
__device__ __align__(256) __nv_bfloat16 g_b2[(size_t)kV * kKV];   // 98.3 MB
__device__ unsigned g_bar_count;
__device__ unsigned g_bar_epoch;

// ---------------------------------------------------------------------------
// h0 = tanh(z @ W_init^T + b_init)
// ---------------------------------------------------------------------------
__global__ void k_h0(const float* __restrict__ z,
                     const float* __restrict__ Wi,
                     const float* __restrict__ bi) {
    int idx = blockIdx.x * blockDim.x + threadIdx.x;
    int b = idx >> 9;
    int j = idx & 511;
    const float* zr = z + b * kDZ;
    const float* wr = Wi + (size_t)j * kDZ;
    float acc = bi[j];
#pragma unroll 8
    for (int d = 0; d < kDZ; d += 4) {
        float4 zv = *(const float4*)(zr + d);
        float4 wv = *(const float4*)(wr + d);
        acc += zv.x * wv.x + zv.y * wv.y + zv.z * wv.z + zv.w * wv.w;
    }
    g_hbuf[0][b * kH + j] = tanhf(acc);
}

// ---------------------------------------------------------------------------
// zpart[b,g] = b_ih[g] + z[b,:] . W_ih[g, E:]
// ---------------------------------------------------------------------------
__global__ void k_zpart(const float* __restrict__ z,
                        const float* __restrict__ W_ih,
                        const float* __restrict__ b_ih) {
    int g = blockIdx.x * blockDim.x + threadIdx.x;
    int b = blockIdx.y;
    const float* zr = z + b * kDZ;
    const float* wr = W_ih + (size_t)g * kLDW + kE;
    float acc = b_ih[g];
#pragma unroll 8
    for (int d = 0; d < kDZ; d += 4) {
        float4 zv = *(const float4*)(zr + d);
        float4 wv = *(const float4*)(wr + d);
        acc += zv.x * wv.x + zv.y * wv.y + zv.z * wv.z + zv.w * wv.w;
    }
    g_zpart[b * kG3H + g] = acc;
}

// ---------------------------------------------------------------------------
// Scalar fp32 SIMT GEMM — used only for gi (6.4 GF).
// ---------------------------------------------------------------------------
__global__ __launch_bounds__(256, 2)
void k_gemm_gi(const float* __restrict__ A, const float* __restrict__ Bm,
               float* __restrict__ C, const float* __restrict__ rowAdd,
               const int* __restrict__ gidx,
               int N, int K, int lda, int ldb) {
    __shared__ float As[16][132];
    __shared__ float Bs[16][132];
    __shared__ int   xs[128];

    const int tid = threadIdx.x;
    const int m0 = blockIdx.y * 128;
    const int n0 = blockIdx.x * 128;
    const int tx = tid & 15;
    const int ty = tid >> 4;

    if (tid < 128) xs[tid] = gidx[m0 + tid];
    __syncthreads();

    float acc[8][8];
#pragma unroll
    for (int i = 0; i < 8; i++)
#pragma unroll
        for (int j = 0; j < 8; j++) acc[i][j] = 0.f;

    for (int k0 = 0; k0 < K; k0 += 16) {
#pragma unroll
        for (int i = 0; i < 2; i++) {
            int f = i * 256 + tid;
            int r = f >> 2;
            int kq = f & 3;
            const float4 av = *(const float4*)(A + (size_t)xs[r] * lda + k0 + kq * 4);
            As[kq * 4 + 0][r] = av.x; As[kq * 4 + 1][r] = av.y;
            As[kq * 4 + 2][r] = av.z; As[kq * 4 + 3][r] = av.w;
            const float4 bv = *(const float4*)(Bm + (size_t)(n0 + r) * ldb + k0 + kq * 4);
            Bs[kq * 4 + 0][r] = bv.x; Bs[kq * 4 + 1][r] = bv.y;
            Bs[kq * 4 + 2][r] = bv.z; Bs[kq * 4 + 3][r] = bv.w;
        }
        __syncthreads();
#pragma unroll
        for (int k = 0; k < 16; k++) {
            float ra[8], rb[8];
            *(float4*)(ra)     = *(const float4*)&As[k][ty * 4];
            *(float4*)(ra + 4) = *(const float4*)&As[k][64 + ty * 4];
            *(float4*)(rb)     = *(const float4*)&Bs[k][tx * 4];
            *(float4*)(rb + 4) = *(const float4*)&Bs[k][64 + tx * 4];
#pragma unroll
            for (int i = 0; i < 8; i++)
#pragma unroll
                for (int j = 0; j < 8; j++) acc[i][j] += ra[i] * rb[j];
        }
        __syncthreads();
    }

#pragma unroll
    for (int i = 0; i < 8; i++) {
        int mloc = (i < 4) ? (ty * 4 + i) : (64 + ty * 4 + (i - 4));
        int m = m0 + mloc;
        float v[8];
#pragma unroll
        for (int j = 0; j < 8; j++) v[j] = acc[i][j];
        const float* ar = rowAdd + (size_t)(m >> 7) * N + n0;
#pragma unroll
        for (int j = 0; j < 4; j++) {
            v[j]     += ar[tx * 4 + j];
            v[4 + j] += ar[64 + tx * 4 + j];
        }
        float* crow = C + (size_t)m * N + n0;
        *(float4*)(crow + tx * 4)      = make_float4(v[0], v[1], v[2], v[3]);
        *(float4*)(crow + 64 + tx * 4) = make_float4(v[4], v[5], v[6], v[7]);
    }
}

// ---------------------------------------------------------------------------
// W_out -> B2 row = [hi | lo | hi]
// ---------------------------------------------------------------------------
__global__ void k_cvtB(const float* __restrict__ src, __nv_bfloat16* __restrict__ dst) {
    int n = blockIdx.x;
    int k2 = threadIdx.x;            // 0..255
    float2 v = *(const float2*)(src + (size_t)n * 512 + k2 * 2);
    __nv_bfloat16 hx = __float2bfloat16(v.x);
    __nv_bfloat16 hy = __float2bfloat16(v.y);
    __nv_bfloat16 lx = __float2bfloat16(v.x - __bfloat162float(hx));
    __nv_bfloat16 ly = __float2bfloat16(v.y - __bfloat162float(hy));
    __nv_bfloat162 hi2(hx, hy), lo2(lx, ly);
    __nv_bfloat162* o = (__nv_bfloat162*)(dst + (size_t)n * kKV);
    o[k2]       = hi2;
    o[256 + k2] = lo2;
    o[512 + k2] = hi2;
}

// ---------------------------------------------------------------------------
// Persistent GRU: 128 blocks x 512 threads, thread = (b, jj, kq).
// LDS.128 inner loop (1 h-load + 3 broadcast w-loads + 6 FFMA2 per 4 k).
// Writes A2 rows ([hi | hi | lo] bf16) directly in the epilogue.
// Grid barrier: atomic count + epoch, pure spin (no nanosleep), bounded.
// ---------------------------------------------------------------------------
__global__ __launch_bounds__(512, 1)
void k_gru_persistent(const float* __restrict__ gi,
                      const float* __restrict__ W_hh,
                      const float* __restrict__ b_hh,
                      float* __restrict__ hbuf,
                      __nv_bfloat16* __restrict__ a2) {
    extern __shared__ float sm[];
    float* wsm = sm;                          // [12][512]
    float* hsm = sm + 12 * kH;                // [32][HPAD]
    float* psm = hsm + kB * HPAD;             // [3][32][4][3]

    const int tid = threadIdx.x;
    const int b  = tid & 31;
    const int jj = (tid >> 5) & 3;
    const int kq = tid >> 7;                  // 0..3
    const int j0 = blockIdx.x * 4;
    const int j  = j0 + jj;

    for (int i = tid; i < 12 * (kH / 4); i += 512) {
        int row = i >> 7;
        int c   = (i & 127) << 2;
        int g = row >> 2, jw = row & 3;
        float4 v = *(const float4*)(W_hh + (size_t)(g * kH + j0 + jw) * kH + c);
        float* d = wsm + row * kH + c;
        d[0] = v.x; d[1] = v.y; d[2] = v.z; d[3] = v.w;
    }

    const float* wrp = wsm + (0 + jj) * kH + kq * 128;
    const float* wzp = wsm + (4 + jj) * kH + kq * 128;
    const float* wnp = wsm + (8 + jj) * kH + kq * 128;
    const float bhr = b_hh[j];
    const float bhz = b_hh[kH + j];
    const float bhn = b_hh[2 * kH + j];
    __syncthreads();

    for (int t = 0; t < kT; t++) {
        const float* hp = hbuf + (size_t)(t & 1) * (kB * kH);
        for (int i = tid; i < kB * (kH / 4); i += 512) {
            int r = i >> 7;
            int c = (i & 127) << 2;
            float4 v = __ldcg((const float4*)(hp + r * kH + c));
            float* d = hsm + r * HPAD + c;
            d[0] = v.x; d[1] = v.y; d[2] = v.z; d[3] = v.w;
        }
        __syncthreads();

        const float* hrow = hsm + b * HPAD + kq * 128;
        u64 ar0 = 0ull, ar1 = 0ull, az0 = 0ull, az1 = 0ull, an0 = 0ull, an1 = 0ull;
#pragma unroll 8
        for (int k = 0; k < 128; k += 4) {
            ulonglong2 h2 = *(const ulonglong2*)(hrow + k);
            ulonglong2 w0 = *(const ulonglong2*)(wrp + k);
            ulonglong2 w1 = *(const ulonglong2*)(wzp + k);
            ulonglong2 w2 = *(const ulonglong2*)(wnp + k);
            ar0 = fma2(h2.x, w0.x, ar0); ar1 = fma2(h2.y, w0.y, ar1);
            az0 = fma2(h2.x, w1.x, az0); az1 = fma2(h2.y, w1.y, az1);
            an0 = fma2(h2.x, w2.x, an0); an1 = fma2(h2.y, w2.y, an1);
        }
        float2 f0, f1;
        f0 = unpack2(ar0); f1 = unpack2(ar1); float pr = f0.x + f0.y + f1.x + f1.y;
        f0 = unpack2(az0); f1 = unpack2(az1); float pz = f0.x + f0.y + f1.x + f1.y;
        f0 = unpack2(an0); f1 = unpack2(an1); float pn = f0.x + f0.y + f1.x + f1.y;

        if (kq) {
            float* p = psm + (((kq - 1) * kB + b) * 4 + jj) * 3;
            p[0] = pr; p[1] = pz; p[2] = pn;
        }
        __syncthreads();
        if (kq == 0) {
#pragma unroll
            for (int q = 0; q < 3; q++) {
                const float* p = psm + ((q * kB + b) * 4 + jj) * 3;
                pr += p[0]; pz += p[1]; pn += p[2];
            }
            const float* gib = gi + ((size_t)b * kT + t) * kG3H;
            float rg = 1.f / (1.f + expf(-(gib[j] + pr + bhr)));
            float zg = 1.f / (1.f + expf(-(gib[kH + j] + pz + bhz)));
            float n  = tanhf(gib[2 * kH + j] + rg * (pn + bhn));
            float hprev = hsm[b * HPAD + j];
            float hn = (1.f - zg) * n + zg * hprev;
            float* hnx = hbuf + (size_t)((t + 1) & 1) * (kB * kH);
            __stcg(hnx + b * kH + j, hn);
            // fused hi/lo split -> A2 row [hi | hi | lo]
            __nv_bfloat16 hi = __float2bfloat16(hn);
            __nv_bfloat16 lo = __float2bfloat16(hn - __bfloat162float(hi));
            __nv_bfloat16* arow = a2 + ((size_t)b * kT + t) * kKV;
            arow[j] = hi;
            arow[512 + j] = hi;
            arow[1024 + j] = lo;
        }
        // ---- grid barrier: atomic count + epoch, pure spin ----
        __syncthreads();
        __threadfence();
        if (tid == 0) {
            unsigned e0 = *((volatile unsigned*)&g_bar_epoch);
            unsigned a = atomicAdd(&g_bar_count, 1u);
            if (a == GRU_NBLK - 1) {
                g_bar_count = 0;
                __threadfence();
                atomicAdd(&g_bar_epoch, 1u);
            } else {
                for (int it = 0; it < (1 << 22); it++) {      // bounded, no sleep
                    if (*((volatile unsigned*)&g_bar_epoch) != e0) break;
                }
                __threadfence();
            }
        }
        __syncthreads();
    }
}

// ---------------------------------------------------------------------------
// Logits GEMM: C[4096,32000] = A2 . B2^T (bf16, K=1536), mma.sync m16n8k16.
// BM=128, BN=256, BK=64; 512 threads = 16 warps (4m x 4n), warp tile 32x64.
// 2-stage cp.async pipeline; xor swizzle; conflict-free ldmatrix.
// ---------------------------------------------------------------------------
__global__ __launch_bounds__(512, 1)
void k_logits_hmma(const __nv_bfloat16* __restrict__ A2,
                   const __nv_bfloat16* __restrict__ B2,
                   float* __restrict__ C) {
    extern __shared__ char smem[];
    const uint32_t sbase = smem_u32(smem);
    const int tid = threadIdx.x;
    const int l = tid & 31;
    const int wid = tid >> 5;
    const int wr = wid & 3;
    const int wc = wid >> 2;
    const int m0 = blockIdx.x * BM;
    const int n0 = blockIdx.y * BN;

    const char* Ag = (const char*)A2 + (size_t)m0 * (kKV * 2);
    const char* Bg = (const char*)B2 + (size_t)n0 * (kKV * 2);

    float acc[2][8][4];
#pragma unroll
    for (int i = 0; i < 2; i++)
#pragma unroll
        for (int j = 0; j < 8; j++)
#pragma unroll
            for (int q = 0; q < 4; q++) acc[i][j][q] = 0.f;

    auto load_stage = [&](int s, int buf) {
        const uint32_t sA = sbase + buf * SMEM_ST;
        const uint32_t sB = sA + SMEM_A_ST;
#pragma unroll
        for (int i = 0; i < 2; i++) {
            int c = i * 512 + tid;
            int r = c >> 3, q = c & 7;
            const char* src = Ag + (size_t)r * (kKV * 2) + s * 128 + q * 16;
            cp_async16(sA + r * 128 + ((q ^ (r & 7)) << 4), src);
        }
#pragma unroll
        for (int i = 0; i < 4; i++) {
            int c = i * 512 + tid;
            int r = c >> 3, q = c & 7;
            const char* src = Bg + (size_t)r * (kKV * 2) + s * 128 + q * 16;
            cp_async16(sB + r * 128 + ((q ^ (r & 7)) << 4), src);
        }
        asm volatile("cp.async.commit_group;" ::: "memory");
    };

    load_stage(0, 0);

    for (int s = 0; s < NSTAGES; s++) {
        if (s + 1 < NSTAGES) {
            load_stage(s + 1, (s + 1) & 1);
            asm volatile("cp.async.wait_group 1;" ::: "memory");
        } else {
            asm volatile("cp.async.wait_group 0;" ::: "memory");
        }
        __syncthreads();

        const uint32_t sA = sbase + (s & 1) * SMEM_ST;
        const uint32_t sB = sA + SMEM_A_ST;
        const uint32_t aRow = sA + (wr * 32 + (l & 15)) * 128;
        const uint32_t bRow = sB + (wc * 64 + (l & 7) + ((l >> 4) << 3)) * 128;

#pragma unroll
        for (int k = 0; k < 4; k++) {
            const uint32_t achunk = (uint32_t)(((2 * k + (l >> 4)) ^ (l & 7)) << 4);
            const uint32_t bchunk = (uint32_t)(((2 * k + ((l >> 3) & 1)) ^ (l & 7)) << 4);
            uint32_t a[2][4];
            ldsm4(a[0][0], a[0][1], a[0][2], a[0][3], aRow + achunk);
            ldsm4(a[1][0], a[1][1], a[1][2], a[1][3], aRow + 16 * 128 + achunk);
            uint32_t b[8][2];
#pragma unroll
            for (int p = 0; p < 4; p++) {
                uint32_t r0, r1, r2, r3;
                ldsm4(r0, r1, r2, r3, bRow + p * (16 * 128) + bchunk);
                b[2 * p][0] = r0;     b[2 * p][1] = r1;
                b[2 * p + 1][0] = r2; b[2 * p + 1][1] = r3;
            }
#pragma unroll
            for (int mf = 0; mf < 2; mf++)
#pragma unroll
                for (int nf = 0; nf < 8; nf++)
                    mma16816(acc[mf][nf], a[mf], b[nf]);
        }
        __syncthreads();
    }

#pragma unroll
    for (int mf = 0; mf < 2; mf++) {
        const int row = m0 + wr * 32 + mf * 16 + (l >> 2);
        float* c0 = C + (size_t)row * kV + n0 + wc * 64 + 2 * (l & 3);
        float* c1 = c0 + (size_t)8 * kV;
#pragma unroll
        for (int nf = 0; nf < 8; nf++) {
            __stcs((float2*)(c0 + nf * 8), make_float2(acc[mf][nf][0], acc[mf][nf][1]));
            __stcs((float2*)(c1 + nf * 8), make_float2(acc[mf][nf][2], acc[mf][nf][3]));
        }
    }
}

// ---------------------------------------------------------------------------
// kernel_launch  (GRU at stream position 4 so ncu's capture window hits it)
// ---------------------------------------------------------------------------
extern "C" void kernel_launch(void* const* d_in, const int* in_sizes, int n_in,
                              void* d_out, int out_size) {
    const int*   x      = (const int*)  d_in[0];
    const float* z      = (const float*)d_in[1];
    const float* emb    = (const float*)d_in[2];
    const float* W_init = (const float*)d_in[3];
    const float* b_init = (const float*)d_in[4];
    const float* W_ih   = (const float*)d_in[5];
    const float* W_hh   = (const float*)d_in[6];
    const float* b_ih   = (const float*)d_in[7];
    const float* b_hh   = (const float*)d_in[8];
    const float* W_out  = (const float*)d_in[9];
    float* out = (float*)d_out;

    float *p_hbuf, *p_zpart, *p_gi;
    __nv_bfloat16 *p_a2, *p_b2;
    cudaGetSymbolAddress((void**)&p_hbuf,  g_hbuf);
    cudaGetSymbolAddress((void**)&p_zpart, g_zpart);
    cudaGetSymbolAddress((void**)&p_gi,    g_gi);
    cudaGetSymbolAddress((void**)&p_a2,    g_a2);
    cudaGetSymbolAddress((void**)&p_b2,    g_b2);

    const int gru_smem = (12 * kH + kB * HPAD + 3 * kB * 4 * 3) * 4;
    cudaFuncSetAttribute(k_gru_persistent,
                         cudaFuncAttributeMaxDynamicSharedMemorySize, gru_smem);
    cudaFuncSetAttribute(k_logits_hmma,
                         cudaFuncAttributeMaxDynamicSharedMemorySize, SMEM_LOGITS);

    // 1-3. prologue + gi
    k_h0<<<64, 256>>>(z, W_init, b_init);
    k_zpart<<<dim3(kG3H / 256, kB), 256>>>(z, W_ih, b_ih);
    k_gemm_gi<<<dim3(kG3H / 128, kMBT / 128), 256>>>(
        emb, W_ih, p_gi, p_zpart, x, kG3H, kE, kE, kLDW);

    // 4. GRU scan (persistent, writes A2 directly)
    k_gru_persistent<<<GRU_NBLK, 512, gru_smem>>>(
        p_gi, W_hh, b_hh, p_hbuf, p_a2);

    // 5. W_out -> B2 = [hi | lo | hi]
    k_cvtB<<<kV, 256>>>(W_out, p_b2);

    // 6. logits: M=4096, N=32000, K=1536 bf16 HMMA
    k_logits_hmma<<<dim3(kMBT / BM, kV / BN), 512, SMEM_LOGITS>>>(
        p_a2, p_b2, out);
}